// round 1
// baseline (speedup 1.0000x reference)
#include <cuda_runtime.h>

#define IMG_D 224
#define HW (IMG_D * IMG_D)
#define NBATCH 64

// One thread per (batch, pixel). Computes all 3 channels for both warped
// images: out[n,ch,p] = M1[n,p]*bilerp4(im1[n,ch], q+C) + M2[n,p]*bilerp4(im2[n,ch], q-C)
// Bilinear uses floor/ceil corners exactly like the reference (ceil, not floor+1,
// so exact-integer coords double-count — matching jax semantics bit-for-bit in fp32).

__device__ __forceinline__ void bilerp_accum(
    const float* __restrict__ plane0,   // &im[n*3*HW]  (channel-0 plane base)
    float x, float y, float m,
    float& a0, float& a1, float& a2)
{
    // clip to [0.001, d-1.001]
    x = fminf(fmaxf(x, 0.001f), (float)IMG_D - 1.001f);
    y = fminf(fmaxf(y, 0.001f), (float)IMG_D - 1.001f);

    float xf = floorf(x), xc = ceilf(x);
    float yf = floorf(y), yc = ceilf(y);

    // weights: w = (1-|x-nx|)*(1-|y-ny|); x>=xf and xc>=x after clip
    float wxf = 1.0f - (x - xf);
    float wxc = 1.0f - (xc - x);
    float wyf = 1.0f - (y - yf);
    float wyc = 1.0f - (yc - y);

    int ixf = (int)xf, ixc = (int)xc;
    int iyf = (int)yf, iyc = (int)yc;

    int i00 = iyf + IMG_D * ixf;   // (xf, yf)
    int i10 = iyf + IMG_D * ixc;   // (xc, yf)
    int i01 = iyc + IMG_D * ixf;   // (xf, yc)
    int i11 = iyc + IMG_D * ixc;   // (xc, yc)

    float w00 = wxf * wyf;
    float w10 = wxc * wyf;
    float w01 = wxf * wyc;
    float w11 = wxc * wyc;

    #pragma unroll
    for (int ch = 0; ch < 3; ch++) {
        const float* base = plane0 + ch * HW;
        float v = w00 * __ldg(base + i00)
                + w10 * __ldg(base + i10)
                + w01 * __ldg(base + i01)
                + w11 * __ldg(base + i11);
        float mv = m * v;
        if (ch == 0) a0 += mv;
        else if (ch == 1) a1 += mv;
        else a2 += mv;
    }
}

__global__ void view_morph_kernel(
    const float* __restrict__ im1,
    const float* __restrict__ im2,
    const float* __restrict__ C,
    const float* __restrict__ M1,
    const float* __restrict__ M2,
    float* __restrict__ out)
{
    int idx = blockIdx.x * blockDim.x + threadIdx.x;
    if (idx >= NBATCH * HW) return;

    int n = idx / HW;
    int p = idx - n * HW;
    int row = p / IMG_D;
    int col = p - row * IMG_D;

    float qx = (float)row;   // q[0] = repeat(arange) -> row index
    float qy = (float)col;   // q[1] = tile(arange)   -> col index

    float cx = C[(size_t)n * 2 * HW + p];          // C[n,0,p]
    float cy = C[(size_t)n * 2 * HW + HW + p];     // C[n,1,p]
    float m1 = M1[(size_t)n * HW + p];
    float m2 = M2[(size_t)n * HW + p];

    float a0 = 0.f, a1 = 0.f, a2 = 0.f;

    const float* im1n = im1 + (size_t)n * 3 * HW;
    const float* im2n = im2 + (size_t)n * 3 * HW;

    bilerp_accum(im1n, qx + cx, qy + cy, m1, a0, a1, a2);
    bilerp_accum(im2n, qx - cx, qy - cy, m2, a0, a1, a2);

    float* outn = out + (size_t)n * 3 * HW;
    outn[p]          = a0;
    outn[HW + p]     = a1;
    outn[2 * HW + p] = a2;
}

extern "C" void kernel_launch(void* const* d_in, const int* in_sizes, int n_in,
                              void* d_out, int out_size)
{
    const float* im1 = (const float*)d_in[0];
    const float* im2 = (const float*)d_in[1];
    const float* C   = (const float*)d_in[2];
    const float* M1  = (const float*)d_in[3];
    const float* M2  = (const float*)d_in[4];
    float* out = (float*)d_out;

    int total = NBATCH * HW;
    int threads = 256;
    int blocks = (total + threads - 1) / threads;
    view_morph_kernel<<<blocks, threads>>>(im1, im2, C, M1, M2, out);
}